// round 2
// baseline (speedup 1.0000x reference)
#include <cuda_runtime.h>
#include <cuda_bf16.h>

// FixedFoveatedSensor: out[b,c,sh,sw] = sum_spp(bilinear(img, warp(pos))*det) / sum_spp(det)
// img [4,3,1024,1024] f32, t [1] f32, jitter [16,256,256,2] f32 -> out [4,3,256,256] f32

#define SENSOR   256
#define IMG_W    1024
#define IMG_H    1024
#define SPP      16
#define NCH      3
#define NBATCH   4

__global__ __launch_bounds__(256, 4)
void foveated_sensor_kernel(const float* __restrict__ img,
                            const float* __restrict__ t,
                            const float* __restrict__ jitter,
                            float* __restrict__ out)
{
    const int p  = blockIdx.x * 256 + threadIdx.x;   // sensor pixel index 0..65535
    const int b  = blockIdx.y;                        // batch 0..3
    const int sw = p & (SENSOR - 1);
    const int sh = p >> 8;

    const float step = 2.0f / (float)SENSOR;          // 0.0078125 exact
    const float pxv = -1.0f + (float)sw * step;
    const float pyv = -1.0f + (float)sh * step;

    const float tt    = __ldg(t);
    const float s     = tanhf(tt);
    const float inv_s = 1.0f / s;

    const float* __restrict__ imgb = img + (size_t)b * NCH * IMG_H * IMG_W;
    const float2* __restrict__ jit = (const float2*)jitter;

    float acc0 = 0.f, acc1 = 0.f, acc2 = 0.f, dsum = 0.f;

#pragma unroll 4
    for (int k = 0; k < SPP; ++k) {
        float2 j = __ldg(&jit[(k << 16) + p]);
        float posx = pxv + j.x * step;
        float posy = pyv + j.y * step;

        float thx = tanhf(tt * posx);
        float thy = tanhf(tt * posy);

        float ddx = tt * (1.0f - thx * thx) * inv_s;
        float ddy = tt * (1.0f - thy * thy) * inv_s;
        float det = ddx * ddy;

        float gx = (thx * inv_s + 1.0f) * (0.5f * IMG_W) - 0.5f;
        float gy = (thy * inv_s + 1.0f) * (0.5f * IMG_H) - 0.5f;
        gx = fminf(fmaxf(gx, 0.0f), (float)(IMG_W - 1));
        gy = fminf(fmaxf(gy, 0.0f), (float)(IMG_H - 1));

        float x0f = floorf(gx);
        float y0f = floorf(gy);
        float wx = gx - x0f;
        float wy = gy - y0f;

        int x0 = (int)x0f;
        int y0 = (int)y0f;
        int x1 = min(x0 + 1, IMG_W - 1);
        int y1 = min(y0 + 1, IMG_H - 1);

        int r0 = y0 << 10;
        int r1 = y1 << 10;

        // channel 0
        {
            const float* ip = imgb;
            float v00 = __ldg(ip + r0 + x0);
            float v01 = __ldg(ip + r0 + x1);
            float v10 = __ldg(ip + r1 + x0);
            float v11 = __ldg(ip + r1 + x1);
            float top = v00 + wx * (v01 - v00);
            float bot = v10 + wx * (v11 - v10);
            acc0 = fmaf((top + wy * (bot - top)), det, acc0);
        }
        // channel 1
        {
            const float* ip = imgb + IMG_H * IMG_W;
            float v00 = __ldg(ip + r0 + x0);
            float v01 = __ldg(ip + r0 + x1);
            float v10 = __ldg(ip + r1 + x0);
            float v11 = __ldg(ip + r1 + x1);
            float top = v00 + wx * (v01 - v00);
            float bot = v10 + wx * (v11 - v10);
            acc1 = fmaf((top + wy * (bot - top)), det, acc1);
        }
        // channel 2
        {
            const float* ip = imgb + 2 * IMG_H * IMG_W;
            float v00 = __ldg(ip + r0 + x0);
            float v01 = __ldg(ip + r0 + x1);
            float v10 = __ldg(ip + r1 + x0);
            float v11 = __ldg(ip + r1 + x1);
            float top = v00 + wx * (v01 - v00);
            float bot = v10 + wx * (v11 - v10);
            acc2 = fmaf((top + wy * (bot - top)), det, acc2);
        }

        dsum += det;
    }

    const float invd = 1.0f / dsum;
    out[(((b * NCH + 0) << 16)) + p] = acc0 * invd;
    out[(((b * NCH + 1) << 16)) + p] = acc1 * invd;
    out[(((b * NCH + 2) << 16)) + p] = acc2 * invd;
}

extern "C" void kernel_launch(void* const* d_in, const int* in_sizes, int n_in,
                              void* d_out, int out_size)
{
    const float* img    = (const float*)d_in[0];
    const float* t      = (const float*)d_in[1];
    const float* jitter = (const float*)d_in[2];
    float* out          = (float*)d_out;

    dim3 grid(SENSOR * SENSOR / 256, NBATCH);
    foveated_sensor_kernel<<<grid, 256>>>(img, t, jitter, out);
}